// round 6
// baseline (speedup 1.0000x reference)
#include <cuda_runtime.h>
#include <cuda_fp16.h>
#include <math.h>

#define NN 100000
#define EE 3200000
#define BB 1000
#define FIN 128
#define SF 12         // fp32 row stride for p
#define SH 16         // fp16 row stride (layer-1 message/accumulator): 32B

// Scratch (static device globals: no allocation anywhere)
__device__ float  g_p  [NN * SF];   // x @ W1[0:128]               (fp32)
__device__ __half g_y  [NN * SH];   // x @ W1[128:256], slot10=1.0 (fp16 message)
__device__ __half g_s1 [NN * SH];   // edge-accumulated y (slot10 = in-degree)
__device__ float  g_zw [NN];        // scalar layer-2 message  zω = h·(W2b@Wfc)
__device__ float  g_s2w[NN];        // edge-accumulated zω
__device__ float2 g_qi [NN];        // {qω = h·(W2a@Wfc), 1/max(deg,1)}
__device__ float  g_g  [BB * 2];    // {Σ h2ω, node count} per graph

__device__ __forceinline__ void red_add_v2_f32(float* p, float a, float b) {
    asm volatile("red.global.add.v2.f32 [%0], {%1,%2};"
                 :: "l"(p), "f"(a), "f"(b) : "memory");
}
__device__ __forceinline__ void red_add_f32(float* p, float a) {
    asm volatile("red.global.add.f32 [%0], %1;" :: "l"(p), "f"(a) : "memory");
}
__device__ __forceinline__ void red_add_v4_h2(void* p, unsigned a, unsigned b, unsigned c, unsigned d) {
    asm volatile("red.global.add.noftz.v4.f16x2 [%0], {%1,%2,%3,%4};"
                 :: "l"(p), "r"(a), "r"(b), "r"(c), "r"(d) : "memory");
}
__device__ __forceinline__ void red_add_v2_h2(void* p, unsigned a, unsigned b) {
    asm volatile("red.global.add.noftz.v2.f16x2 [%0], {%1,%2};"
                 :: "l"(p), "r"(a), "r"(b) : "memory");
}

__device__ __forceinline__ unsigned pack_h2(float lo, float hi) {
    __half2 h = __floats2half2_rn(lo, hi);
    return *(unsigned*)&h;
}
__device__ __forceinline__ unsigned long long pack_f32x2(float lo, float hi) {
    unsigned long long r;
    asm("mov.b64 %0, {%1,%2};" : "=l"(r) : "f"(lo), "f"(hi));
    return r;
}
__device__ __forceinline__ void unpack_f32x2(float& lo, float& hi, unsigned long long v) {
    asm("mov.b64 {%0,%1}, %2;" : "=f"(lo), "=f"(hi) : "l"(v));
}
__device__ __forceinline__ void fma_f32x2(unsigned long long& acc,
                                          unsigned long long a, unsigned long long b) {
    asm("fma.rn.f32x2 %0, %1, %2, %0;" : "+l"(acc) : "l"(a), "l"(b));
}

// ---------------------------------------------------------------------------
// K1: p = x @ W1[0:128,:] (fp32), y = x @ W1[128:256,:] (fp16, slot10=1.0)
//     Also zeroes g_s1 row, g_s2w entry, and (n<BB) g_g entry.
// ---------------------------------------------------------------------------
__global__ void k1_project(const float* __restrict__ x, const float* __restrict__ W1) {
    __shared__ __align__(16) float sW[2 * FIN * 10];   // 10 KB
    for (int i = threadIdx.x; i < 2 * FIN * 10; i += blockDim.x) sW[i] = W1[i];
    __syncthreads();

    int n = blockIdx.x * blockDim.x + threadIdx.x;
    if (n >= NN) return;

    // zero all accumulators for this launch
    uint4 zz = {0, 0, 0, 0};
    uint4* s1r = (uint4*)(g_s1 + (size_t)n * SH);
    s1r[0] = zz; s1r[1] = zz;
    g_s2w[n] = 0.f;
    if (n < BB) { g_g[2 * n] = 0.f; g_g[2 * n + 1] = 0.f; }

    unsigned long long accP[5], accY[5];
#pragma unroll
    for (int j = 0; j < 5; j++) { accP[j] = 0ull; accY[j] = 0ull; }

    const float4* xr = (const float4*)(x + (size_t)n * FIN);
#pragma unroll 4
    for (int f4 = 0; f4 < FIN / 4; f4++) {
        float4 xv = xr[f4];
        float xf[4] = {xv.x, xv.y, xv.z, xv.w};
#pragma unroll
        for (int k = 0; k < 4; k++) {
            int f = f4 * 4 + k;
            unsigned long long bx = pack_f32x2(xf[k], xf[k]);
            const unsigned long long* wp = (const unsigned long long*)&sW[f * 10];
            const unsigned long long* wy = (const unsigned long long*)&sW[(FIN + f) * 10];
#pragma unroll
            for (int j = 0; j < 5; j++) {
                fma_f32x2(accP[j], bx, wp[j]);
                fma_f32x2(accY[j], bx, wy[j]);
            }
        }
    }

    float* pr = g_p + (size_t)n * SF;
    float yv[10];
#pragma unroll
    for (int j = 0; j < 5; j++) {
        float lo, hi;
        unpack_f32x2(lo, hi, accP[j]);
        pr[2 * j] = lo; pr[2 * j + 1] = hi;
        unpack_f32x2(yv[2 * j], yv[2 * j + 1], accY[j]);
    }

    uint4 u0, u1;
    u0.x = pack_h2(yv[0], yv[1]);
    u0.y = pack_h2(yv[2], yv[3]);
    u0.z = pack_h2(yv[4], yv[5]);
    u0.w = pack_h2(yv[6], yv[7]);
    u1.x = pack_h2(yv[8], yv[9]);
    u1.y = pack_h2(1.0f, 0.0f);     // degree carrier
    u1.z = 0; u1.w = 0;
    uint4* yr = (uint4*)(g_y + (size_t)n * SH);
    yr[0] = u0; yr[1] = u1;
}

// ---------------------------------------------------------------------------
// K2: layer-1 edge scatter fp16 (2 REDs/edge), 4 edges per thread.
// ---------------------------------------------------------------------------
__global__ void k_edge_scatter1(const int* __restrict__ src, const int* __restrict__ dst,
                                const __half* __restrict__ msg, __half* __restrict__ acc) {
    int t = blockIdx.x * blockDim.x + threadIdx.x;   // t in [0, EE/4)
    int4 s4 = ((const int4*)src)[t];
    int4 d4 = ((const int4*)dst)[t];
    int ss[4] = {s4.x, s4.y, s4.z, s4.w};
    int dd[4] = {d4.x, d4.y, d4.z, d4.w};

    uint4 a[4]; uint2 b[4];
#pragma unroll
    for (int k = 0; k < 4; k++) {
        const uint4* v = (const uint4*)(msg + (size_t)ss[k] * SH);
        a[k] = v[0];
        b[k] = ((const uint2*)v)[2];
    }
#pragma unroll
    for (int k = 0; k < 4; k++) {
        __half* o = acc + (size_t)dd[k] * SH;
        red_add_v4_h2(o,     a[k].x, a[k].y, a[k].z, a[k].w);
        red_add_v2_h2(o + 8, b[k].x, b[k].y);
    }
}

// ---------------------------------------------------------------------------
// K3: h = relu(p + s1/deg); qω = h·(W2a@Wfc); zω = h·(W2b@Wfc)
//     Writes g_zw (scatter2 message), g_qi = {qω, 1/deg}.
// ---------------------------------------------------------------------------
__global__ void k3_layer2in(const float* __restrict__ W2, const float* __restrict__ Wfc) {
    __shared__ float sWa[10], sWb[10];
    if (threadIdx.x < 20) {
        int k = threadIdx.x;            // row of W2 [20 x 10]
        float v = 0.f;
#pragma unroll
        for (int j = 0; j < 10; j++) v += W2[k * 10 + j] * Wfc[j];
        if (k < 10) sWa[k] = v; else sWb[k - 10] = v;
    }
    __syncthreads();

    int n = blockIdx.x * blockDim.x + threadIdx.x;
    if (n >= NN) return;

    const float* pr = g_p + (size_t)n * SF;
    const uint4* sv = (const uint4*)(g_s1 + (size_t)n * SH);
    uint4 a = sv[0];
    uint2 b = ((const uint2*)sv)[2];

    float s[12];
    {
        float2 t;
        t = __half22float2(*(__half2*)&a.x); s[0] = t.x; s[1] = t.y;
        t = __half22float2(*(__half2*)&a.y); s[2] = t.x; s[3] = t.y;
        t = __half22float2(*(__half2*)&a.z); s[4] = t.x; s[5] = t.y;
        t = __half22float2(*(__half2*)&a.w); s[6] = t.x; s[7] = t.y;
        t = __half22float2(*(__half2*)&b.x); s[8] = t.x; s[9] = t.y;
        t = __half22float2(*(__half2*)&b.y); s[10] = t.x; s[11] = t.y;
    }
    float inv = 1.f / fmaxf(s[10], 1.f);

    float qw = 0.f, zw = 0.f;
#pragma unroll
    for (int j = 0; j < 10; j++) {
        float h = fmaxf(pr[j] + s[j] * inv, 0.f);
        qw += h * sWa[j];
        zw += h * sWb[j];
    }

    g_zw[n] = zw;
    g_qi[n] = make_float2(qw, inv);
}

// ---------------------------------------------------------------------------
// K4: layer-2 edge scatter — ONE scalar fp32 RED per edge.
// ---------------------------------------------------------------------------
__global__ void k_edge_scatter2(const int* __restrict__ src, const int* __restrict__ dst) {
    int t = blockIdx.x * blockDim.x + threadIdx.x;   // t in [0, EE/4)
    int4 s4 = ((const int4*)src)[t];
    int4 d4 = ((const int4*)dst)[t];
    float v0 = g_zw[s4.x];
    float v1 = g_zw[s4.y];
    float v2 = g_zw[s4.z];
    float v3 = g_zw[s4.w];
    red_add_f32(&g_s2w[d4.x], v0);
    red_add_f32(&g_s2w[d4.y], v1);
    red_add_f32(&g_s2w[d4.z], v2);
    red_add_f32(&g_s2w[d4.w], v3);
}

// ---------------------------------------------------------------------------
// K5: h2ω = qω + s2ω/deg; pool {h2ω, 1} into g_g[batch[n]]
// ---------------------------------------------------------------------------
__global__ void k5_pool(const int* __restrict__ batch) {
    int n = blockIdx.x * blockDim.x + threadIdx.x;
    if (n >= NN) return;
    float2 qi = g_qi[n];
    float h2w = qi.x + g_s2w[n] * qi.y;
    red_add_v2_f32(&g_g[2 * batch[n]], h2w, 1.0f);
}

// ---------------------------------------------------------------------------
// K6: out[b] = sigmoid( Σh2ω / cnt )
// ---------------------------------------------------------------------------
__global__ void k6_head(float* __restrict__ out) {
    int b = blockIdx.x * blockDim.x + threadIdx.x;
    if (b >= BB) return;
    float sum = g_g[2 * b];
    float cnt = g_g[2 * b + 1];
    float v = sum / fmaxf(cnt, 1.f);
    out[b] = 1.f / (1.f + expf(-v));
}

// ---------------------------------------------------------------------------
extern "C" void kernel_launch(void* const* d_in, const int* in_sizes, int n_in,
                              void* d_out, int out_size) {
    const float* x     = (const float*)d_in[0];
    const int*   ei    = (const int*)  d_in[1];   // src = ei[0:E), dst = ei[E:2E)
    const int*   batch = (const int*)  d_in[2];
    const float* W1    = (const float*)d_in[3];
    const float* W2    = (const float*)d_in[4];
    const float* Wfc   = (const float*)d_in[5];
    float*       out   = (float*)d_out;

    void *p_y, *p_s1;
    cudaGetSymbolAddress(&p_y,  g_y);
    cudaGetSymbolAddress(&p_s1, g_s1);

    const int T = 256;
    k1_project     <<<(NN + T - 1) / T, T>>>(x, W1);
    k_edge_scatter1<<<EE / 4 / T, T>>>(ei, ei + EE, (const __half*)p_y, (__half*)p_s1);
    k3_layer2in    <<<(NN + T - 1) / T, T>>>(W2, Wfc);
    k_edge_scatter2<<<EE / 4 / T, T>>>(ei, ei + EE);
    k5_pool        <<<(NN + T - 1) / T, T>>>(batch);
    k6_head        <<<(BB + T - 1) / T, T>>>(out);
}

// round 7
// speedup vs baseline: 1.6085x; 1.6085x over previous
#include <cuda_runtime.h>
#include <cuda_fp16.h>
#include <math.h>

#define NN 100000
#define EE 3200000
#define BB 1000
#define FIN 128
#define SF 12         // fp32 row stride for p
#define SH 16         // fp16 row stride (layer-1 message/accumulator): 32B
#define SW 8          // fp32 stride for s2w: 32B -> private L2 sector per node

// Scratch (static device globals: no allocation anywhere)
__device__ float  g_p  [NN * SF];   // x @ W1[0:128]               (fp32)
__device__ __half g_y  [NN * SH];   // x @ W1[128:256], slot10=1.0 (fp16 message)
__device__ __half g_s1 [NN * SH];   // edge-accumulated y (slot10 = in-degree)
__device__ float  g_zw [NN];        // scalar layer-2 message  zω = h·(W2b@Wfc)
__device__ float  g_s2w[NN * SW];   // edge-accumulated zω (padded: 1 sector/node)
__device__ float2 g_qi [NN];        // {qω = h·(W2a@Wfc), 1/max(deg,1)}
__device__ float  g_g  [BB * 2];    // {Σ h2ω, node count} per graph

__device__ __forceinline__ void red_add_v2_f32(float* p, float a, float b) {
    asm volatile("red.global.add.v2.f32 [%0], {%1,%2};"
                 :: "l"(p), "f"(a), "f"(b) : "memory");
}
__device__ __forceinline__ void red_add_f32(float* p, float a) {
    asm volatile("red.global.add.f32 [%0], %1;" :: "l"(p), "f"(a) : "memory");
}
__device__ __forceinline__ void red_add_v4_h2(void* p, unsigned a, unsigned b, unsigned c, unsigned d) {
    asm volatile("red.global.add.noftz.v4.f16x2 [%0], {%1,%2,%3,%4};"
                 :: "l"(p), "r"(a), "r"(b), "r"(c), "r"(d) : "memory");
}
__device__ __forceinline__ void red_add_v2_h2(void* p, unsigned a, unsigned b) {
    asm volatile("red.global.add.noftz.v2.f16x2 [%0], {%1,%2};"
                 :: "l"(p), "r"(a), "r"(b) : "memory");
}

__device__ __forceinline__ unsigned pack_h2(float lo, float hi) {
    __half2 h = __floats2half2_rn(lo, hi);
    return *(unsigned*)&h;
}
__device__ __forceinline__ unsigned long long pack_f32x2(float lo, float hi) {
    unsigned long long r;
    asm("mov.b64 %0, {%1,%2};" : "=l"(r) : "f"(lo), "f"(hi));
    return r;
}
__device__ __forceinline__ void unpack_f32x2(float& lo, float& hi, unsigned long long v) {
    asm("mov.b64 {%0,%1}, %2;" : "=f"(lo), "=f"(hi) : "l"(v));
}
__device__ __forceinline__ void fma_f32x2(unsigned long long& acc,
                                          unsigned long long a, unsigned long long b) {
    asm("fma.rn.f32x2 %0, %1, %2, %0;" : "+l"(acc) : "l"(a), "l"(b));
}

// ---------------------------------------------------------------------------
// K1: p = x @ W1[0:128,:] (fp32), y = x @ W1[128:256,:] (fp16, slot10=1.0)
//     Also zeroes g_s1 row, g_s2w row, and (n<BB) g_g entry.
// ---------------------------------------------------------------------------
__global__ void k1_project(const float* __restrict__ x, const float* __restrict__ W1) {
    __shared__ __align__(16) float sW[2 * FIN * 10];   // 10 KB
    for (int i = threadIdx.x; i < 2 * FIN * 10; i += blockDim.x) sW[i] = W1[i];
    __syncthreads();

    int n = blockIdx.x * blockDim.x + threadIdx.x;
    if (n >= NN) return;

    // zero all accumulators for this launch
    uint4 zz = {0, 0, 0, 0};
    uint4* s1r = (uint4*)(g_s1 + (size_t)n * SH);
    s1r[0] = zz; s1r[1] = zz;
    uint4* s2r = (uint4*)(g_s2w + (size_t)n * SW);
    s2r[0] = zz; s2r[1] = zz;
    if (n < BB) { g_g[2 * n] = 0.f; g_g[2 * n + 1] = 0.f; }

    unsigned long long accP[5], accY[5];
#pragma unroll
    for (int j = 0; j < 5; j++) { accP[j] = 0ull; accY[j] = 0ull; }

    const float4* xr = (const float4*)(x + (size_t)n * FIN);
#pragma unroll 4
    for (int f4 = 0; f4 < FIN / 4; f4++) {
        float4 xv = xr[f4];
        float xf[4] = {xv.x, xv.y, xv.z, xv.w};
#pragma unroll
        for (int k = 0; k < 4; k++) {
            int f = f4 * 4 + k;
            unsigned long long bx = pack_f32x2(xf[k], xf[k]);
            const unsigned long long* wp = (const unsigned long long*)&sW[f * 10];
            const unsigned long long* wy = (const unsigned long long*)&sW[(FIN + f) * 10];
#pragma unroll
            for (int j = 0; j < 5; j++) {
                fma_f32x2(accP[j], bx, wp[j]);
                fma_f32x2(accY[j], bx, wy[j]);
            }
        }
    }

    float* pr = g_p + (size_t)n * SF;
    float yv[10];
#pragma unroll
    for (int j = 0; j < 5; j++) {
        float lo, hi;
        unpack_f32x2(lo, hi, accP[j]);
        pr[2 * j] = lo; pr[2 * j + 1] = hi;
        unpack_f32x2(yv[2 * j], yv[2 * j + 1], accY[j]);
    }

    uint4 u0, u1;
    u0.x = pack_h2(yv[0], yv[1]);
    u0.y = pack_h2(yv[2], yv[3]);
    u0.z = pack_h2(yv[4], yv[5]);
    u0.w = pack_h2(yv[6], yv[7]);
    u1.x = pack_h2(yv[8], yv[9]);
    u1.y = pack_h2(1.0f, 0.0f);     // degree carrier
    u1.z = 0; u1.w = 0;
    uint4* yr = (uint4*)(g_y + (size_t)n * SH);
    yr[0] = u0; yr[1] = u1;
}

// ---------------------------------------------------------------------------
// K2: layer-1 edge scatter fp16 (2 REDs/edge), 4 edges per thread.
// ---------------------------------------------------------------------------
__global__ void k_edge_scatter1(const int* __restrict__ src, const int* __restrict__ dst,
                                const __half* __restrict__ msg, __half* __restrict__ acc) {
    int t = blockIdx.x * blockDim.x + threadIdx.x;   // t in [0, EE/4)
    int4 s4 = ((const int4*)src)[t];
    int4 d4 = ((const int4*)dst)[t];
    int ss[4] = {s4.x, s4.y, s4.z, s4.w};
    int dd[4] = {d4.x, d4.y, d4.z, d4.w};

    uint4 a[4]; uint2 b[4];
#pragma unroll
    for (int k = 0; k < 4; k++) {
        const uint4* v = (const uint4*)(msg + (size_t)ss[k] * SH);
        a[k] = v[0];
        b[k] = ((const uint2*)v)[2];
    }
#pragma unroll
    for (int k = 0; k < 4; k++) {
        __half* o = acc + (size_t)dd[k] * SH;
        red_add_v4_h2(o,     a[k].x, a[k].y, a[k].z, a[k].w);
        red_add_v2_h2(o + 8, b[k].x, b[k].y);
    }
}

// ---------------------------------------------------------------------------
// K3: h = relu(p + s1/deg); qω = h·(W2a@Wfc); zω = h·(W2b@Wfc)
// ---------------------------------------------------------------------------
__global__ void k3_layer2in(const float* __restrict__ W2, const float* __restrict__ Wfc) {
    __shared__ float sWa[10], sWb[10];
    if (threadIdx.x < 20) {
        int k = threadIdx.x;            // row of W2 [20 x 10]
        float v = 0.f;
#pragma unroll
        for (int j = 0; j < 10; j++) v += W2[k * 10 + j] * Wfc[j];
        if (k < 10) sWa[k] = v; else sWb[k - 10] = v;
    }
    __syncthreads();

    int n = blockIdx.x * blockDim.x + threadIdx.x;
    if (n >= NN) return;

    const float* pr = g_p + (size_t)n * SF;
    const uint4* sv = (const uint4*)(g_s1 + (size_t)n * SH);
    uint4 a = sv[0];
    uint2 b = ((const uint2*)sv)[2];

    float s[12];
    {
        float2 t;
        t = __half22float2(*(__half2*)&a.x); s[0] = t.x; s[1] = t.y;
        t = __half22float2(*(__half2*)&a.y); s[2] = t.x; s[3] = t.y;
        t = __half22float2(*(__half2*)&a.z); s[4] = t.x; s[5] = t.y;
        t = __half22float2(*(__half2*)&a.w); s[6] = t.x; s[7] = t.y;
        t = __half22float2(*(__half2*)&b.x); s[8] = t.x; s[9] = t.y;
        t = __half22float2(*(__half2*)&b.y); s[10] = t.x; s[11] = t.y;
    }
    float inv = 1.f / fmaxf(s[10], 1.f);

    float qw = 0.f, zw = 0.f;
#pragma unroll
    for (int j = 0; j < 10; j++) {
        float h = fmaxf(pr[j] + s[j] * inv, 0.f);
        qw += h * sWa[j];
        zw += h * sWb[j];
    }

    g_zw[n] = zw;
    g_qi[n] = make_float2(qw, inv);
}

// ---------------------------------------------------------------------------
// K4: layer-2 edge scatter — ONE scalar fp32 RED per edge to a PRIVATE sector.
// ---------------------------------------------------------------------------
__global__ void k_edge_scatter2(const int* __restrict__ src, const int* __restrict__ dst) {
    int t = blockIdx.x * blockDim.x + threadIdx.x;   // t in [0, EE/4)
    int4 s4 = ((const int4*)src)[t];
    int4 d4 = ((const int4*)dst)[t];
    float v0 = g_zw[s4.x];
    float v1 = g_zw[s4.y];
    float v2 = g_zw[s4.z];
    float v3 = g_zw[s4.w];
    red_add_f32(&g_s2w[(size_t)d4.x * SW], v0);
    red_add_f32(&g_s2w[(size_t)d4.y * SW], v1);
    red_add_f32(&g_s2w[(size_t)d4.z * SW], v2);
    red_add_f32(&g_s2w[(size_t)d4.w * SW], v3);
}

// ---------------------------------------------------------------------------
// K5: h2ω = qω + s2ω/deg; segmented warp-reduce over sorted batch, then
//     only segment heads RED into g_g[b]. Cuts pool REDs ~25x.
// ---------------------------------------------------------------------------
__global__ void k5_pool(const int* __restrict__ batch) {
    int n = blockIdx.x * blockDim.x + threadIdx.x;
    int lane = threadIdx.x & 31;

    int b = -1;
    float v = 0.f, c = 0.f;
    if (n < NN) {
        float2 qi = g_qi[n];
        v = qi.x + g_s2w[(size_t)n * SW] * qi.y;
        c = 1.f;
        b = batch[n];
    }

    // segmented suffix sum over contiguous equal-b runs (batch sorted)
#pragma unroll
    for (int off = 1; off < 32; off <<= 1) {
        float v2 = __shfl_down_sync(0xffffffff, v, off);
        float c2 = __shfl_down_sync(0xffffffff, c, off);
        int   b2 = __shfl_down_sync(0xffffffff, b, off);
        if (lane + off < 32 && b2 == b) { v += v2; c += c2; }
    }
    int bprev = __shfl_up_sync(0xffffffff, b, 1);
    bool head = (lane == 0) || (bprev != b);
    if (head && b >= 0)
        red_add_v2_f32(&g_g[2 * b], v, c);
}

// ---------------------------------------------------------------------------
// K6: out[b] = sigmoid( Σh2ω / cnt )
// ---------------------------------------------------------------------------
__global__ void k6_head(float* __restrict__ out) {
    int b = blockIdx.x * blockDim.x + threadIdx.x;
    if (b >= BB) return;
    float sum = g_g[2 * b];
    float cnt = g_g[2 * b + 1];
    float v = sum / fmaxf(cnt, 1.f);
    out[b] = 1.f / (1.f + expf(-v));
}

// ---------------------------------------------------------------------------
extern "C" void kernel_launch(void* const* d_in, const int* in_sizes, int n_in,
                              void* d_out, int out_size) {
    const float* x     = (const float*)d_in[0];
    const int*   ei    = (const int*)  d_in[1];   // src = ei[0:E), dst = ei[E:2E)
    const int*   batch = (const int*)  d_in[2];
    const float* W1    = (const float*)d_in[3];
    const float* W2    = (const float*)d_in[4];
    const float* Wfc   = (const float*)d_in[5];
    float*       out   = (float*)d_out;

    void *p_y, *p_s1;
    cudaGetSymbolAddress(&p_y,  g_y);
    cudaGetSymbolAddress(&p_s1, g_s1);

    const int T = 256;
    k1_project     <<<(NN + T - 1) / T, T>>>(x, W1);
    k_edge_scatter1<<<EE / 4 / T, T>>>(ei, ei + EE, (const __half*)p_y, (__half*)p_s1);
    k3_layer2in    <<<(NN + T - 1) / T, T>>>(W2, Wfc);
    k_edge_scatter2<<<EE / 4 / T, T>>>(ei, ei + EE);
    k5_pool        <<<(NN + T - 1) / T, T>>>(batch);
    k6_head        <<<(BB + T - 1) / T, T>>>(out);
}